// round 6
// baseline (speedup 1.0000x reference)
#include <cuda_runtime.h>
#include <cstdint>
#include <math.h>

// Problem constants
#define BATCH 4
#define T 4096
#define D 512
#define CHK 128
#define NQC 32
#define WKEYS 384               // decay^256/(1-decay) ~ 8e-5 tail (validated rd5)
#define MTOT 16384

#define XN (BATCH * T * D)

// Scratch (intermediates stored tf32-rounded at epilogues)
__device__ float g_q [XN];
__device__ float g_k [XN];
__device__ float g_vT[BATCH * D * T];   // V transposed: [b][d][t]
__device__ float g_ws[BATCH * NQC * CHK * WKEYS];
__device__ float g_r [XN];

// ---------------------------------------------------------------------------
// helpers
// ---------------------------------------------------------------------------
__device__ __forceinline__ float tf32r(float x) {
    float r;
    asm("cvt.rna.tf32.f32 %0, %1;" : "=f"(r) : "f"(x));
    return r;
}
__device__ __forceinline__ void mma8(float* c, const float* a, const float* b) {
    asm volatile(
        "mma.sync.aligned.m16n8k8.row.col.f32.tf32.tf32.f32 "
        "{%0,%1,%2,%3}, {%4,%5,%6,%7}, {%8,%9}, {%0,%1,%2,%3};\n"
        : "+f"(c[0]), "+f"(c[1]), "+f"(c[2]), "+f"(c[3])
        : "r"(__float_as_uint(a[0])), "r"(__float_as_uint(a[1])),
          "r"(__float_as_uint(a[2])), "r"(__float_as_uint(a[3])),
          "r"(__float_as_uint(b[0])), "r"(__float_as_uint(b[1])));
}

// ---------------------------------------------------------------------------
// Permuted-pair smem layout for a 128x16 K-major tile (2048 floats, 8 KB):
//   addr(r, k) = r*16 + 2*(((k&3) + 4*((k>>3)&1)) ^ (r&7)) + ((k>>2)&1)
// -> every mma fragment pair (k, k+4) is a contiguous float2 (LDS.64),
//    XOR-swizzled so conflicts are at most 2-way.
// CTA 128x128, 4 warps (2x2), warp tile 64x64, BK=16, double-buffered.
// ---------------------------------------------------------------------------

// Gmem fetch: thread (tid) covers rows r = (tid>>2)+32*it, k = (tid&3)+4j.
// Each LDG.32 instruction is 16B-contiguous across the 4 lanes of a quad.
__device__ __forceinline__ void ldg_p(float* v, const float* __restrict__ g,
                                      int ld, int tid)
{
    const int c2 = tid & 3;
#pragma unroll
    for (int it = 0; it < 4; it++) {
        const float* row = g + (size_t)((tid >> 2) + it * 32) * ld;
        v[it * 4 + 0] = row[c2];
        v[it * 4 + 1] = row[c2 + 4];
        v[it * 4 + 2] = row[c2 + 8];
        v[it * 4 + 3] = row[c2 + 12];
    }
}

// Store to permuted layout; optional tf32 rounding (skip when source is
// already tf32-rounded in memory).
template <bool RND>
__device__ __forceinline__ void sts_p(float* sbf, const float* v, int tid)
{
    const int c2 = tid & 3;
#pragma unroll
    for (int it = 0; it < 4; it++) {
        int r = (tid >> 2) + it * 32;
        float* rp = sbf + r * 16;
        int sw = r & 7;
        float a0 = v[it * 4 + 0], a1 = v[it * 4 + 1];
        float a2 = v[it * 4 + 2], a3 = v[it * 4 + 3];
        if (RND) { a0 = tf32r(a0); a1 = tf32r(a1); a2 = tf32r(a2); a3 = tf32r(a3); }
        *(float2*)(rp + 2 * (c2 ^ sw))       = make_float2(a0, a1);   // kbh=0
        *(float2*)(rp + 2 * ((c2 + 4) ^ sw)) = make_float2(a2, a3);   // kbh=1
    }
}

// MMA over one 16-deep stage. As/Bs point to permuted tiles.
__device__ __forceinline__ void mma_stage(
    const float* __restrict__ As, const float* __restrict__ Bs,
    float acc[4][8][4], int wm, int wn, int g, int c)
{
#pragma unroll
    for (int kbh = 0; kbh < 2; kbh++) {
        const int sw2 = 2 * ((c + 4 * kbh) ^ g);   // (R&7)==g for all frag rows
        float a[4][4];
#pragma unroll
        for (int mi = 0; mi < 4; mi++) {
            int R0 = wm + mi * 16 + g;
            float2 p0 = *(const float2*)(As + R0 * 16 + sw2);
            float2 p1 = *(const float2*)(As + (R0 + 8) * 16 + sw2);
            a[mi][0] = p0.x; a[mi][1] = p1.x; a[mi][2] = p0.y; a[mi][3] = p1.y;
        }
#pragma unroll
        for (int ni = 0; ni < 8; ni++) {
            int Rb = wn + ni * 8 + g;
            float2 q = *(const float2*)(Bs + Rb * 16 + sw2);
            float b2[2] = { q.x, q.y };
#pragma unroll
            for (int mi = 0; mi < 4; mi++)
                mma8(acc[mi][ni], a[mi], b2);
        }
    }
}

// Core: acc += A[128,K] * B[128,K]^T (both K-major), K = nkt*16.
template <bool RA, bool RB>
__device__ __forceinline__ void gemm_core(
    const float* __restrict__ A, int lda,
    const float* __restrict__ B, int ldb,
    int nkt, float acc[4][8][4], float* sm,
    int tid, int wm, int wn, int g, int c)
{
    float va[16], vb[16];
    ldg_p(va, A, lda, tid);
    ldg_p(vb, B, ldb, tid);
    sts_p<RA>(sm, va, tid);
    sts_p<RB>(sm + 2048, vb, tid);
    __syncthreads();
    int s = 0;
    for (int it = 1; it <= nkt; it++) {
        if (it < nkt) {
            ldg_p(va, A + it * 16, lda, tid);
            ldg_p(vb, B + it * 16, ldb, tid);
        }
        mma_stage(sm + s * 4096, sm + s * 4096 + 2048, acc, wm, wn, g, c);
        if (it < nkt) {
            sts_p<RA>(sm + (s ^ 1) * 4096, va, tid);
            sts_p<RB>(sm + (s ^ 1) * 4096 + 2048, vb, tid);
        }
        __syncthreads();
        s ^= 1;
    }
}

#define GEMM_PROLOGUE()                                     \
    __shared__ float sm[8192];                              \
    float acc[4][8][4];                                     \
    _Pragma("unroll")                                       \
    for (int i = 0; i < 4; i++)                             \
        _Pragma("unroll")                                   \
        for (int j = 0; j < 8; j++)                         \
            _Pragma("unroll")                               \
            for (int q = 0; q < 4; q++) acc[i][j][q] = 0.f; \
    const int tid = threadIdx.x;                            \
    const int warp = tid >> 5, lane = tid & 31;             \
    const int wm = (warp >> 1) * 64, wn = (warp & 1) * 64;  \
    const int g = lane >> 2, c = lane & 3;

// ---------------------------------------------------------------------------
// Kernel 1: QKV. z=0 -> Q, z=1 -> K (row-major), z=2 -> V transposed.
// ---------------------------------------------------------------------------
__global__ __launch_bounds__(128, 2) void qkv_gemm(
    const float* __restrict__ x,
    const float* __restrict__ Wq,
    const float* __restrict__ Wk,
    const float* __restrict__ Wv)
{
    GEMM_PROLOGUE();
    const int z = blockIdx.z;
    const float* W = (z == 0) ? Wq : (z == 1) ? Wk : Wv;
    const int row0 = blockIdx.y * 128, col0 = blockIdx.x * 128;
    const float* A = x + (size_t)row0 * D;
    const float* B = W + (size_t)col0 * D;

    gemm_core<true, true>(A, D, B, D, D / 16, acc, sm, tid, wm, wn, g, c);

    if (z < 2) {
        float* Cp = ((z == 0) ? g_q : g_k) + (size_t)row0 * D + col0;
#pragma unroll
        for (int mi = 0; mi < 4; mi++)
#pragma unroll
            for (int ni = 0; ni < 8; ni++) {
                int row = wm + mi * 16 + g;
                int col = wn + ni * 8 + 2 * c;
                *(float2*)&Cp[(size_t)row * D + col] =
                    make_float2(tf32r(acc[mi][ni][0]), tf32r(acc[mi][ni][1]));
                *(float2*)&Cp[(size_t)(row + 8) * D + col] =
                    make_float2(tf32r(acc[mi][ni][2]), tf32r(acc[mi][ni][3]));
            }
    } else {
        const int b = row0 >> 12;
        const int t0 = row0 & (T - 1);
#pragma unroll
        for (int mi = 0; mi < 4; mi++)
#pragma unroll
            for (int ni = 0; ni < 8; ni++) {
                int t = t0 + wm + mi * 16 + g;
                int col = col0 + wn + ni * 8 + 2 * c;
                float* base0 = g_vT + ((size_t)b * D + col) * T;
                float* base1 = base0 + T;
                base0[t]     = tf32r(acc[mi][ni][0]);
                base1[t]     = tf32r(acc[mi][ni][1]);
                base0[t + 8] = tf32r(acc[mi][ni][2]);
                base1[t + 8] = tf32r(acc[mi][ni][3]);
            }
    }
}

// ---------------------------------------------------------------------------
// Kernel 2: banded scores + decay weights -> g_ws (tf32-rounded).
// col tiles are always fully inside kvalid (both multiples of 128).
// ---------------------------------------------------------------------------
__global__ __launch_bounds__(128, 2) void scores_gemm(const float* __restrict__ decay_logit)
{
    const int bid = blockIdx.y;
    const int b = bid >> 5, qc = bid & 31;
    const int col0 = blockIdx.x * 128;
    const int kvalid = T - qc * CHK;
    if (col0 >= kvalid) return;

    GEMM_PROLOGUE();
    const float* A = g_q + (size_t)(b * T + qc * CHK) * D;
    const float* B = g_k + (size_t)(b * T + qc * CHK + col0) * D;

    gemm_core<false, false>(A, D, B, D, D / 16, acc, sm, tid, wm, wn, g, c);

    const float dl = *decay_logit;
    const float decay = 1.f / (1.f + expf(-dl));
    const float l2d = log2f(decay);
    float* WS = g_ws + (size_t)(b * NQC + qc) * CHK * WKEYS;

#pragma unroll
    for (int mi = 0; mi < 4; mi++)
#pragma unroll
        for (int ni = 0; ni < 8; ni++) {
#pragma unroll
            for (int half = 0; half < 2; half++) {
                int ti = wm + mi * 16 + g + half * 8;
                float2 o;
#pragma unroll
                for (int e = 0; e < 2; e++) {
                    int jj = col0 + wn + ni * 8 + 2 * c + e;
                    int diff = jj - ti;
                    float w = (diff > 0) ? exp2f((float)(diff - 1) * l2d) : 0.f;
                    float v = tf32r(acc[mi][ni][half * 2 + e] * w);
                    if (e == 0) o.x = v; else o.y = v;
                }
                int jj0 = col0 + wn + ni * 8 + 2 * c;
                *(float2*)&WS[(size_t)ti * WKEYS + jj0] = o;
            }
        }
}

// ---------------------------------------------------------------------------
// Kernel 3: retrieved = WS @ V_window (NT against g_vT), tf32-rounded store.
// ---------------------------------------------------------------------------
__global__ __launch_bounds__(128, 2) void retrv_gemm()
{
    GEMM_PROLOGUE();
    const int bid = blockIdx.y;
    const int b = bid >> 5, qc = bid & 31;
    const int col0 = blockIdx.x * 128;
    const int kvalid = T - qc * CHK;
    const int keff = (kvalid < WKEYS) ? kvalid : WKEYS;
    const int nkt = keff / 16;

    const float* A = g_ws + (size_t)(b * NQC + qc) * CHK * WKEYS;
    const float* B = g_vT + ((size_t)b * D + col0) * T + qc * CHK;

    gemm_core<false, false>(A, WKEYS, B, T, nkt, acc, sm, tid, wm, wn, g, c);

    float* Cp = g_r + (size_t)(b * T + qc * CHK) * D + col0;
#pragma unroll
    for (int mi = 0; mi < 4; mi++)
#pragma unroll
        for (int ni = 0; ni < 8; ni++) {
            int row = wm + mi * 16 + g;
            int col = wn + ni * 8 + 2 * c;
            *(float2*)&Cp[(size_t)row * D + col] =
                make_float2(tf32r(acc[mi][ni][0]), tf32r(acc[mi][ni][1]));
            *(float2*)&Cp[(size_t)(row + 8) * D + col] =
                make_float2(tf32r(acc[mi][ni][2]), tf32r(acc[mi][ni][3]));
        }
}

// ---------------------------------------------------------------------------
// Kernel 4: out = (R @ Wo^T) * out_scale   (Wo raw -> RB rounds)
// ---------------------------------------------------------------------------
__global__ __launch_bounds__(128, 2) void out_gemm(
    const float* __restrict__ Wo,
    const float* __restrict__ out_scale,
    float* __restrict__ out)
{
    GEMM_PROLOGUE();
    const int row0 = blockIdx.y * 128, col0 = blockIdx.x * 128;
    const float* A = g_r + (size_t)row0 * D;
    const float* B = Wo + (size_t)col0 * D;

    gemm_core<false, true>(A, D, B, D, D / 16, acc, sm, tid, wm, wn, g, c);

    const float sc = *out_scale;
    float* Cp = out + (size_t)row0 * D + col0;
#pragma unroll
    for (int mi = 0; mi < 4; mi++)
#pragma unroll
        for (int ni = 0; ni < 8; ni++) {
            int row = wm + mi * 16 + g;
            int col = wn + ni * 8 + 2 * c;
            *(float2*)&Cp[(size_t)row * D + col] =
                make_float2(acc[mi][ni][0] * sc, acc[mi][ni][1] * sc);
            *(float2*)&Cp[(size_t)(row + 8) * D + col] =
                make_float2(acc[mi][ni][2] * sc, acc[mi][ni][3] * sc);
        }
}

// ---------------------------------------------------------------------------
extern "C" void kernel_launch(void* const* d_in, const int* in_sizes, int n_in,
                              void* d_out, int out_size)
{
    const float* x  = (const float*)d_in[0];
    const float* Wq = (const float*)d_in[1];
    const float* Wk = (const float*)d_in[2];
    const float* Wv = (const float*)d_in[3];
    const float* Wo = (const float*)d_in[4];
    const float* dl = (const float*)d_in[5];
    const float* os = (const float*)d_in[6];
    float* out = (float*)d_out;

    dim3 blk(128);
    qkv_gemm   <<<dim3(4, MTOT / 128, 3), blk>>>(x, Wq, Wk, Wv);
    scores_gemm<<<dim3(WKEYS / 128, BATCH * NQC), blk>>>(dl);
    retrv_gemm <<<dim3(4, BATCH * NQC), blk>>>();
    out_gemm   <<<dim3(4, MTOT / 128), blk>>>(Wo, os, out);
}

// round 7
// speedup vs baseline: 1.2567x; 1.2567x over previous
#include <cuda_runtime.h>
#include <cstdint>
#include <math.h>

// Problem constants
#define BATCH 4
#define T 4096
#define D 512
#define CHK 128
#define NQC 32
#define WKEYS 384               // decay^256/(1-decay) ~ 8e-5 tail (validated)
#define MTOT 16384

#define XN (BATCH * T * D)

// Scratch (intermediates stored tf32-rounded at epilogues)
__device__ float g_q [XN];
__device__ float g_k [XN];
__device__ float g_vT[BATCH * D * T];   // V transposed: [b][d][t]
__device__ float g_ws[BATCH * NQC * CHK * WKEYS];
__device__ float g_r [XN];

// ---------------------------------------------------------------------------
// helpers
// ---------------------------------------------------------------------------
__device__ __forceinline__ float tf32r(float x) {
    float r;
    asm("cvt.rna.tf32.f32 %0, %1;" : "=f"(r) : "f"(x));
    return r;
}
__device__ __forceinline__ void mma8(float* c, const float* a, const float* b) {
    asm volatile(
        "mma.sync.aligned.m16n8k8.row.col.f32.tf32.tf32.f32 "
        "{%0,%1,%2,%3}, {%4,%5,%6,%7}, {%8,%9}, {%0,%1,%2,%3};\n"
        : "+f"(c[0]), "+f"(c[1]), "+f"(c[2]), "+f"(c[3])
        : "r"(__float_as_uint(a[0])), "r"(__float_as_uint(a[1])),
          "r"(__float_as_uint(a[2])), "r"(__float_as_uint(a[3])),
          "r"(__float_as_uint(b[0])), "r"(__float_as_uint(b[1])));
}

// ---------------------------------------------------------------------------
// Pair layout for a 128x16 K-major tile: row pitch 18 floats (9 float2).
// Element pair (k, k+4), k = (kp&3) + 8*(kp>>2), stored as float2 at
// float2-unit address  r*9 + kp,  kp in [0,8).
// Bank math (float2 banks, mod 16): 9R is a bijection over R mod 16, so
// fragment loads (R varies by g, kp by c) are at most 2-way conflicted.
// Tile = 128*18 floats = 9216 B. Stage = A+B = 18432 B; 2 stages = 36864 B.
// CTA 128x128, 4 warps (2x2), warp tile 64x64, BK=16, double-buffered.
// ---------------------------------------------------------------------------
#define PITCH 18
#define TILE_F (128 * PITCH)        // floats per tile
#define STAGE_F (2 * TILE_F)        // A + B

// LDG.128 x4: thread covers k in [8h, 8h+8) of rows (tid>>1) and (tid>>1)+64.
__device__ __forceinline__ void ldg_pair(float4* v, const float* __restrict__ g,
                                         int ld, int tid)
{
    const int r = tid >> 1, h = tid & 1;
    const float* p0 = g + (size_t)r * ld + 8 * h;
    const float* p1 = g + (size_t)(r + 64) * ld + 8 * h;
    v[0] = *(const float4*)p0;
    v[1] = *(const float4*)(p0 + 4);
    v[2] = *(const float4*)p1;
    v[3] = *(const float4*)(p1 + 4);
}

// STS.64 x8: pairs (v[2rr][j], v[2rr+1][j]) -> kp = 4h + j of row r + 64rr.
template <bool RND>
__device__ __forceinline__ void sts_pair(float* sbf, const float4* v, int tid)
{
    const int r = tid >> 1, h = tid & 1;
#pragma unroll
    for (int rr = 0; rr < 2; rr++) {
        float* rp = sbf + (r + 64 * rr) * PITCH + 8 * h;
        const float* lo = (const float*)&v[2 * rr];       // k = 8h + 0..3
        const float* hi = (const float*)&v[2 * rr + 1];   // k = 8h + 4..7
#pragma unroll
        for (int j = 0; j < 4; j++) {
            float x = lo[j], y = hi[j];
            if (RND) { x = tf32r(x); y = tf32r(y); }
            *(float2*)(rp + 2 * j) = make_float2(x, y);
        }
    }
}

// MMA over one 16-deep stage (two k-halves of 8).
__device__ __forceinline__ void mma_stage(
    const float* __restrict__ As, const float* __restrict__ Bs,
    float acc[4][8][4], int wm, int wn, int g, int c)
{
#pragma unroll
    for (int kbh = 0; kbh < 2; kbh++) {
        const int off = 2 * (c + 4 * kbh);   // float offset within row
        float a[4][4];
#pragma unroll
        for (int mi = 0; mi < 4; mi++) {
            int R0 = wm + mi * 16 + g;
            float2 p0 = *(const float2*)(As + R0 * PITCH + off);
            float2 p1 = *(const float2*)(As + (R0 + 8) * PITCH + off);
            a[mi][0] = p0.x; a[mi][1] = p1.x; a[mi][2] = p0.y; a[mi][3] = p1.y;
        }
#pragma unroll
        for (int ni = 0; ni < 8; ni++) {
            int Rb = wn + ni * 8 + g;
            float2 q = *(const float2*)(Bs + Rb * PITCH + off);
            float b2[2] = { q.x, q.y };
#pragma unroll
            for (int mi = 0; mi < 4; mi++)
                mma8(acc[mi][ni], a[mi], b2);
        }
    }
}

// Core: acc += A[128,K] * B[128,K]^T (both K-major), K = nkt*16.
template <bool RA, bool RB>
__device__ __forceinline__ void gemm_core(
    const float* __restrict__ A, int lda,
    const float* __restrict__ B, int ldb,
    int nkt, float acc[4][8][4], float* sm,
    int tid, int wm, int wn, int g, int c)
{
    float4 va[4], vb[4];
    ldg_pair(va, A, lda, tid);
    ldg_pair(vb, B, ldb, tid);
    sts_pair<RA>(sm, va, tid);
    sts_pair<RB>(sm + TILE_F, vb, tid);
    __syncthreads();
    int s = 0;
    for (int it = 1; it <= nkt; it++) {
        if (it < nkt) {
            ldg_pair(va, A + it * 16, lda, tid);
            ldg_pair(vb, B + it * 16, ldb, tid);
        }
        mma_stage(sm + s * STAGE_F, sm + s * STAGE_F + TILE_F, acc, wm, wn, g, c);
        if (it < nkt) {
            sts_pair<RA>(sm + (s ^ 1) * STAGE_F, va, tid);
            sts_pair<RB>(sm + (s ^ 1) * STAGE_F + TILE_F, vb, tid);
        }
        __syncthreads();
        s ^= 1;
    }
}

#define GEMM_PROLOGUE()                                     \
    __shared__ float sm[2 * STAGE_F];                       \
    float acc[4][8][4];                                     \
    _Pragma("unroll")                                       \
    for (int i = 0; i < 4; i++)                             \
        _Pragma("unroll")                                   \
        for (int j = 0; j < 8; j++)                         \
            _Pragma("unroll")                               \
            for (int q = 0; q < 4; q++) acc[i][j][q] = 0.f; \
    const int tid = threadIdx.x;                            \
    const int warp = tid >> 5, lane = tid & 31;             \
    const int wm = (warp >> 1) * 64, wn = (warp & 1) * 64;  \
    const int g = lane >> 2, c = lane & 3;

// ---------------------------------------------------------------------------
// Kernel 1: QKV. z=0 -> Q, z=1 -> K (row-major), z=2 -> V transposed.
// ---------------------------------------------------------------------------
__global__ __launch_bounds__(128, 2) void qkv_gemm(
    const float* __restrict__ x,
    const float* __restrict__ Wq,
    const float* __restrict__ Wk,
    const float* __restrict__ Wv)
{
    GEMM_PROLOGUE();
    const int z = blockIdx.z;
    const float* W = (z == 0) ? Wq : (z == 1) ? Wk : Wv;
    const int row0 = blockIdx.y * 128, col0 = blockIdx.x * 128;
    const float* A = x + (size_t)row0 * D;
    const float* B = W + (size_t)col0 * D;

    gemm_core<true, true>(A, D, B, D, D / 16, acc, sm, tid, wm, wn, g, c);

    if (z < 2) {
        float* Cp = ((z == 0) ? g_q : g_k) + (size_t)row0 * D + col0;
#pragma unroll
        for (int mi = 0; mi < 4; mi++)
#pragma unroll
            for (int ni = 0; ni < 8; ni++) {
                int row = wm + mi * 16 + g;
                int col = wn + ni * 8 + 2 * c;
                *(float2*)&Cp[(size_t)row * D + col] =
                    make_float2(tf32r(acc[mi][ni][0]), tf32r(acc[mi][ni][1]));
                *(float2*)&Cp[(size_t)(row + 8) * D + col] =
                    make_float2(tf32r(acc[mi][ni][2]), tf32r(acc[mi][ni][3]));
            }
    } else {
        const int b = row0 >> 12;
        const int t0 = row0 & (T - 1);
#pragma unroll
        for (int mi = 0; mi < 4; mi++)
#pragma unroll
            for (int ni = 0; ni < 8; ni++) {
                int t = t0 + wm + mi * 16 + g;
                int col = col0 + wn + ni * 8 + 2 * c;
                float* base0 = g_vT + ((size_t)b * D + col) * T;
                float* base1 = base0 + T;
                base0[t]     = tf32r(acc[mi][ni][0]);
                base1[t]     = tf32r(acc[mi][ni][1]);
                base0[t + 8] = tf32r(acc[mi][ni][2]);
                base1[t + 8] = tf32r(acc[mi][ni][3]);
            }
    }
}

// ---------------------------------------------------------------------------
// Kernel 2: banded scores + decay weights -> g_ws (tf32-rounded).
// ---------------------------------------------------------------------------
__global__ __launch_bounds__(128, 2) void scores_gemm(const float* __restrict__ decay_logit)
{
    const int bid = blockIdx.y;
    const int b = bid >> 5, qc = bid & 31;
    const int col0 = blockIdx.x * 128;
    const int kvalid = T - qc * CHK;
    if (col0 >= kvalid) return;   // tile fully out of range; never read

    GEMM_PROLOGUE();
    const float* A = g_q + (size_t)(b * T + qc * CHK) * D;
    const float* B = g_k + (size_t)(b * T + qc * CHK + col0) * D;

    gemm_core<false, false>(A, D, B, D, D / 16, acc, sm, tid, wm, wn, g, c);

    const float dl = *decay_logit;
    const float decay = 1.f / (1.f + expf(-dl));
    const float l2d = log2f(decay);
    float* WS = g_ws + (size_t)(b * NQC + qc) * CHK * WKEYS;

#pragma unroll
    for (int mi = 0; mi < 4; mi++)
#pragma unroll
        for (int ni = 0; ni < 8; ni++) {
#pragma unroll
            for (int half = 0; half < 2; half++) {
                int ti = wm + mi * 16 + g + half * 8;
                float2 o;
#pragma unroll
                for (int e = 0; e < 2; e++) {
                    int jj = col0 + wn + ni * 8 + 2 * c + e;
                    int diff = jj - ti;
                    float w = (diff > 0) ? exp2f((float)(diff - 1) * l2d) : 0.f;
                    float v = tf32r(acc[mi][ni][half * 2 + e] * w);
                    if (e == 0) o.x = v; else o.y = v;
                }
                int jj0 = col0 + wn + ni * 8 + 2 * c;
                *(float2*)&WS[(size_t)ti * WKEYS + jj0] = o;
            }
        }
}

// ---------------------------------------------------------------------------
// Kernel 3: retrieved = WS @ V_window (NT against g_vT), tf32-rounded store.
// keff is a multiple of 128, so all k-tiles are fully valid.
// ---------------------------------------------------------------------------
__global__ __launch_bounds__(128, 2) void retrv_gemm()
{
    GEMM_PROLOGUE();
    const int bid = blockIdx.y;
    const int b = bid >> 5, qc = bid & 31;
    const int col0 = blockIdx.x * 128;
    const int kvalid = T - qc * CHK;
    const int keff = (kvalid < WKEYS) ? kvalid : WKEYS;
    const int nkt = keff / 16;

    const float* A = g_ws + (size_t)(b * NQC + qc) * CHK * WKEYS;
    const float* B = g_vT + ((size_t)b * D + col0) * T + qc * CHK;

    gemm_core<false, false>(A, WKEYS, B, T, nkt, acc, sm, tid, wm, wn, g, c);

    float* Cp = g_r + (size_t)(b * T + qc * CHK) * D + col0;
#pragma unroll
    for (int mi = 0; mi < 4; mi++)
#pragma unroll
        for (int ni = 0; ni < 8; ni++) {
            int row = wm + mi * 16 + g;
            int col = wn + ni * 8 + 2 * c;
            *(float2*)&Cp[(size_t)row * D + col] =
                make_float2(tf32r(acc[mi][ni][0]), tf32r(acc[mi][ni][1]));
            *(float2*)&Cp[(size_t)(row + 8) * D + col] =
                make_float2(tf32r(acc[mi][ni][2]), tf32r(acc[mi][ni][3]));
        }
}

// ---------------------------------------------------------------------------
// Kernel 4: out = (R @ Wo^T) * out_scale   (Wo raw -> RB rounds)
// ---------------------------------------------------------------------------
__global__ __launch_bounds__(128, 2) void out_gemm(
    const float* __restrict__ Wo,
    const float* __restrict__ out_scale,
    float* __restrict__ out)
{
    GEMM_PROLOGUE();
    const int row0 = blockIdx.y * 128, col0 = blockIdx.x * 128;
    const float* A = g_r + (size_t)row0 * D;
    const float* B = Wo + (size_t)col0 * D;

    gemm_core<false, true>(A, D, B, D, D / 16, acc, sm, tid, wm, wn, g, c);

    const float sc = *out_scale;
    float* Cp = out + (size_t)row0 * D + col0;
#pragma unroll
    for (int mi = 0; mi < 4; mi++)
#pragma unroll
        for (int ni = 0; ni < 8; ni++) {
            int row = wm + mi * 16 + g;
            int col = wn + ni * 8 + 2 * c;
            *(float2*)&Cp[(size_t)row * D + col] =
                make_float2(acc[mi][ni][0] * sc, acc[mi][ni][1] * sc);
            *(float2*)&Cp[(size_t)(row + 8) * D + col] =
                make_float2(acc[mi][ni][2] * sc, acc[mi][ni][3] * sc);
        }
}

// ---------------------------------------------------------------------------
extern "C" void kernel_launch(void* const* d_in, const int* in_sizes, int n_in,
                              void* d_out, int out_size)
{
    const float* x  = (const float*)d_in[0];
    const float* Wq = (const float*)d_in[1];
    const float* Wk = (const float*)d_in[2];
    const float* Wv = (const float*)d_in[3];
    const float* Wo = (const float*)d_in[4];
    const float* dl = (const float*)d_in[5];
    const float* os = (const float*)d_in[6];
    float* out = (float*)d_out;

    dim3 blk(128);
    qkv_gemm   <<<dim3(4, MTOT / 128, 3), blk>>>(x, Wq, Wk, Wv);
    scores_gemm<<<dim3(WKEYS / 128, BATCH * NQC), blk>>>(dl);
    retrv_gemm <<<dim3(4, BATCH * NQC), blk>>>();
    out_gemm   <<<dim3(4, MTOT / 128), blk>>>(Wo, os, out);
}

// round 8
// speedup vs baseline: 1.9566x; 1.5569x over previous
#include <cuda_runtime.h>
#include <cuda_fp16.h>
#include <cstdint>
#include <math.h>

// Problem constants
#define BATCH 4
#define T 4096
#define D 512
#define CHK 128
#define NQC 32
#define WKEYS 384               // decay^256/(1-decay) ~ 8e-5 tail (validated)
#define MTOT 16384

#define XN (BATCH * T * D)

// Scratch: intermediates stored as fp16 (same mantissa precision as tf32)
__device__ __align__(16) __half g_q [XN];
__device__ __align__(16) __half g_k [XN];
__device__ __align__(16) __half g_vT[BATCH * D * T];   // V transposed: [b][d][t]
__device__ __align__(16) __half g_ws[BATCH * NQC * CHK * WKEYS];
__device__ __align__(16) __half g_r [XN];

// ---------------------------------------------------------------------------
// helpers
// ---------------------------------------------------------------------------
__device__ __forceinline__ uint32_t f2h2(float x, float y) {
    __half2 h = __floats2half2_rn(x, y);
    return *(uint32_t*)&h;
}

// m16n8k16 fp16 MMA, fp32 accumulate.
__device__ __forceinline__ void mma16(float* c, const uint32_t* a,
                                      uint32_t b0, uint32_t b1) {
    asm volatile(
        "mma.sync.aligned.m16n8k16.row.col.f32.f16.f16.f32 "
        "{%0,%1,%2,%3}, {%4,%5,%6,%7}, {%8,%9}, {%0,%1,%2,%3};\n"
        : "+f"(c[0]), "+f"(c[1]), "+f"(c[2]), "+f"(c[3])
        : "r"(a[0]), "r"(a[1]), "r"(a[2]), "r"(a[3]), "r"(b0), "r"(b1));
}

// ---------------------------------------------------------------------------
// Smem tile: 128 rows x 16 halves (K-major), row pitch 24 halves = 12 b32.
// Fragment LDS addr (b32) = R*12 + c (+4). 12g+c mod 32 is a perfect
// permutation over the warp -> conflict-free LDS.32.
// Tile = 1536 b32 (6 KB); stage (A+B) = 3072 b32; 2 stages = 24 KB.
// CTA 128x128, 4 warps (2x2), warp tile 64x64, BK=16, double-buffered.
// ---------------------------------------------------------------------------
#define TILE32 1536
#define STAGE32 3072

// Gmem fetch, half source: rows r=tid>>1, r+64; 8 halves (16 B) at k=8h.
__device__ __forceinline__ void ldg_tile(uint4* v, const __half* __restrict__ g,
                                         int ld, int tid)
{
    const int r = tid >> 1, h = tid & 1;
    v[0] = *(const uint4*)(g + (size_t)r * ld + 8 * h);
    v[1] = *(const uint4*)(g + (size_t)(r + 64) * ld + 8 * h);
}

// Gmem fetch, float source: 2x LDG.128 per row, convert to 8 halves.
__device__ __forceinline__ void ldg_tile(uint4* v, const float* __restrict__ g,
                                         int ld, int tid)
{
    const int r = tid >> 1, h = tid & 1;
    const float* p0 = g + (size_t)r * ld + 8 * h;
    const float* p1 = g + (size_t)(r + 64) * ld + 8 * h;
    float4 a = *(const float4*)p0, b = *(const float4*)(p0 + 4);
    v[0] = make_uint4(f2h2(a.x, a.y), f2h2(a.z, a.w), f2h2(b.x, b.y), f2h2(b.z, b.w));
    float4 e = *(const float4*)p1, f = *(const float4*)(p1 + 4);
    v[1] = make_uint4(f2h2(e.x, e.y), f2h2(e.z, e.w), f2h2(f.x, f.y), f2h2(f.z, f.w));
}

// STS.128 x2 into the pitched tile.
__device__ __forceinline__ void sts_tile(uint32_t* sb, const uint4* v, int tid)
{
    const int r = tid >> 1, h = tid & 1;
    *(uint4*)(sb + r * 12 + 4 * h) = v[0];
    *(uint4*)(sb + (r + 64) * 12 + 4 * h) = v[1];
}

// MMA over one 16-deep stage: 32 LDS.32 + 32 MMAs per warp.
__device__ __forceinline__ void mma_stage(
    const uint32_t* __restrict__ As, const uint32_t* __restrict__ Bs,
    float acc[4][8][4], int wm, int wn, int g, int c)
{
    uint32_t a[4][4];
#pragma unroll
    for (int mi = 0; mi < 4; mi++) {
        int R = wm + mi * 16 + g;
        a[mi][0] = As[R * 12 + c];
        a[mi][1] = As[(R + 8) * 12 + c];
        a[mi][2] = As[R * 12 + c + 4];
        a[mi][3] = As[(R + 8) * 12 + c + 4];
    }
#pragma unroll
    for (int ni = 0; ni < 8; ni++) {
        int Rb = wn + ni * 8 + g;
        uint32_t b0 = Bs[Rb * 12 + c];
        uint32_t b1 = Bs[Rb * 12 + c + 4];
#pragma unroll
        for (int mi = 0; mi < 4; mi++)
            mma16(acc[mi][ni], a[mi], b0, b1);
    }
}

// Core: acc += A[128,K] * B[128,K]^T (both K-major), K = nkt*16.
template <typename TA, typename TB>
__device__ __forceinline__ void gemm_core(
    const TA* __restrict__ A, int lda,
    const TB* __restrict__ B, int ldb,
    int nkt, float acc[4][8][4], uint32_t* sm,
    int tid, int wm, int wn, int g, int c)
{
    uint4 va[2], vb[2];
    ldg_tile(va, A, lda, tid);
    ldg_tile(vb, B, ldb, tid);
    sts_tile(sm, va, tid);
    sts_tile(sm + TILE32, vb, tid);
    __syncthreads();
    int s = 0;
    for (int it = 1; it <= nkt; it++) {
        if (it < nkt) {
            ldg_tile(va, A + it * 16, lda, tid);
            ldg_tile(vb, B + it * 16, ldb, tid);
        }
        mma_stage(sm + s * STAGE32, sm + s * STAGE32 + TILE32, acc, wm, wn, g, c);
        if (it < nkt) {
            sts_tile(sm + (s ^ 1) * STAGE32, va, tid);
            sts_tile(sm + (s ^ 1) * STAGE32 + TILE32, vb, tid);
        }
        __syncthreads();
        s ^= 1;
    }
}

#define GEMM_PROLOGUE()                                     \
    __shared__ uint32_t sm[2 * STAGE32];                    \
    float acc[4][8][4];                                     \
    _Pragma("unroll")                                       \
    for (int i = 0; i < 4; i++)                             \
        _Pragma("unroll")                                   \
        for (int j = 0; j < 8; j++)                         \
            _Pragma("unroll")                               \
            for (int q = 0; q < 4; q++) acc[i][j][q] = 0.f; \
    const int tid = threadIdx.x;                            \
    const int warp = tid >> 5, lane = tid & 31;             \
    const int wm = (warp >> 1) * 64, wn = (warp & 1) * 64;  \
    const int g = lane >> 2, c = lane & 3;

// ---------------------------------------------------------------------------
// Kernel 1: QKV. z=0 -> Q, z=1 -> K (row-major half), z=2 -> V transposed.
// ---------------------------------------------------------------------------
__global__ __launch_bounds__(128, 2) void qkv_gemm(
    const float* __restrict__ x,
    const float* __restrict__ Wq,
    const float* __restrict__ Wk,
    const float* __restrict__ Wv)
{
    GEMM_PROLOGUE();
    const int z = blockIdx.z;
    const float* W = (z == 0) ? Wq : (z == 1) ? Wk : Wv;
    const int row0 = blockIdx.y * 128, col0 = blockIdx.x * 128;
    const float* A = x + (size_t)row0 * D;
    const float* B = W + (size_t)col0 * D;

    gemm_core(A, D, B, D, D / 16, acc, sm, tid, wm, wn, g, c);

    if (z < 2) {
        __half* Cp = ((z == 0) ? g_q : g_k) + (size_t)row0 * D + col0;
#pragma unroll
        for (int mi = 0; mi < 4; mi++)
#pragma unroll
            for (int ni = 0; ni < 8; ni++) {
                int row = wm + mi * 16 + g;
                int col = wn + ni * 8 + 2 * c;
                *(__half2*)&Cp[(size_t)row * D + col] =
                    __floats2half2_rn(acc[mi][ni][0], acc[mi][ni][1]);
                *(__half2*)&Cp[(size_t)(row + 8) * D + col] =
                    __floats2half2_rn(acc[mi][ni][2], acc[mi][ni][3]);
            }
    } else {
        const int b = row0 >> 12;
        const int t0 = row0 & (T - 1);
#pragma unroll
        for (int mi = 0; mi < 4; mi++)
#pragma unroll
            for (int ni = 0; ni < 8; ni++) {
                int t = t0 + wm + mi * 16 + g;
                int col = col0 + wn + ni * 8 + 2 * c;
                __half* base0 = g_vT + ((size_t)b * D + col) * T;
                __half* base1 = base0 + T;
                base0[t]     = __float2half_rn(acc[mi][ni][0]);
                base1[t]     = __float2half_rn(acc[mi][ni][1]);
                base0[t + 8] = __float2half_rn(acc[mi][ni][2]);
                base1[t + 8] = __float2half_rn(acc[mi][ni][3]);
            }
    }
}

// ---------------------------------------------------------------------------
// Kernel 2: banded scores + decay weights -> g_ws (half).
// ---------------------------------------------------------------------------
__global__ __launch_bounds__(128, 2) void scores_gemm(const float* __restrict__ decay_logit)
{
    const int bid = blockIdx.y;
    const int b = bid >> 5, qc = bid & 31;
    const int col0 = blockIdx.x * 128;
    const int kvalid = T - qc * CHK;
    if (col0 >= kvalid) return;   // tile fully out of range; never read

    GEMM_PROLOGUE();
    const __half* A = g_q + (size_t)(b * T + qc * CHK) * D;
    const __half* B = g_k + (size_t)(b * T + qc * CHK + col0) * D;

    gemm_core(A, D, B, D, D / 16, acc, sm, tid, wm, wn, g, c);

    const float dl = *decay_logit;
    const float decay = 1.f / (1.f + expf(-dl));
    const float l2d = log2f(decay);
    __half* WS = g_ws + (size_t)(b * NQC + qc) * CHK * WKEYS;

#pragma unroll
    for (int mi = 0; mi < 4; mi++)
#pragma unroll
        for (int ni = 0; ni < 8; ni++) {
#pragma unroll
            for (int half_ = 0; half_ < 2; half_++) {
                int ti = wm + mi * 16 + g + half_ * 8;
                float v0, v1;
#pragma unroll
                for (int e = 0; e < 2; e++) {
                    int jj = col0 + wn + ni * 8 + 2 * c + e;
                    int diff = jj - ti;
                    float w = (diff > 0) ? exp2f((float)(diff - 1) * l2d) : 0.f;
                    float v = acc[mi][ni][half_ * 2 + e] * w;
                    if (e == 0) v0 = v; else v1 = v;
                }
                int jj0 = col0 + wn + ni * 8 + 2 * c;
                *(__half2*)&WS[(size_t)ti * WKEYS + jj0] = __floats2half2_rn(v0, v1);
            }
        }
}

// ---------------------------------------------------------------------------
// Kernel 3: retrieved = WS @ V_window (NT against g_vT) -> g_r (half).
// keff is a multiple of 128 -> all k-tiles fully valid.
// ---------------------------------------------------------------------------
__global__ __launch_bounds__(128, 2) void retrv_gemm()
{
    GEMM_PROLOGUE();
    const int bid = blockIdx.y;
    const int b = bid >> 5, qc = bid & 31;
    const int col0 = blockIdx.x * 128;
    const int kvalid = T - qc * CHK;
    const int keff = (kvalid < WKEYS) ? kvalid : WKEYS;
    const int nkt = keff / 16;

    const __half* A = g_ws + (size_t)(b * NQC + qc) * CHK * WKEYS;
    const __half* B = g_vT + ((size_t)b * D + col0) * T + qc * CHK;

    gemm_core(A, WKEYS, B, T, nkt, acc, sm, tid, wm, wn, g, c);

    __half* Cp = g_r + (size_t)(b * T + qc * CHK) * D + col0;
#pragma unroll
    for (int mi = 0; mi < 4; mi++)
#pragma unroll
        for (int ni = 0; ni < 8; ni++) {
            int row = wm + mi * 16 + g;
            int col = wn + ni * 8 + 2 * c;
            *(__half2*)&Cp[(size_t)row * D + col] =
                __floats2half2_rn(acc[mi][ni][0], acc[mi][ni][1]);
            *(__half2*)&Cp[(size_t)(row + 8) * D + col] =
                __floats2half2_rn(acc[mi][ni][2], acc[mi][ni][3]);
        }
}

// ---------------------------------------------------------------------------
// Kernel 4: out = (R @ Wo^T) * out_scale   (float output)
// ---------------------------------------------------------------------------
__global__ __launch_bounds__(128, 2) void out_gemm(
    const float* __restrict__ Wo,
    const float* __restrict__ out_scale,
    float* __restrict__ out)
{
    GEMM_PROLOGUE();
    const int row0 = blockIdx.y * 128, col0 = blockIdx.x * 128;
    const __half* A = g_r + (size_t)row0 * D;
    const float* B = Wo + (size_t)col0 * D;

    gemm_core(A, D, B, D, D / 16, acc, sm, tid, wm, wn, g, c);

    const float sc = *out_scale;
    float* Cp = out + (size_t)row0 * D + col0;
#pragma unroll
    for (int mi = 0; mi < 4; mi++)
#pragma unroll
        for (int ni = 0; ni < 8; ni++) {
            int row = wm + mi * 16 + g;
            int col = wn + ni * 8 + 2 * c;
            *(float2*)&Cp[(size_t)row * D + col] =
                make_float2(acc[mi][ni][0] * sc, acc[mi][ni][1] * sc);
            *(float2*)&Cp[(size_t)(row + 8) * D + col] =
                make_float2(acc[mi][ni][2] * sc, acc[mi][ni][3] * sc);
        }
}

// ---------------------------------------------------------------------------
extern "C" void kernel_launch(void* const* d_in, const int* in_sizes, int n_in,
                              void* d_out, int out_size)
{
    const float* x  = (const float*)d_in[0];
    const float* Wq = (const float*)d_in[1];
    const float* Wk = (const float*)d_in[2];
    const float* Wv = (const float*)d_in[3];
    const float* Wo = (const float*)d_in[4];
    const float* dl = (const float*)d_in[5];
    const float* os = (const float*)d_in[6];
    float* out = (float*)d_out;

    dim3 blk(128);
    qkv_gemm   <<<dim3(4, MTOT / 128, 3), blk>>>(x, Wq, Wk, Wv);
    scores_gemm<<<dim3(WKEYS / 128, BATCH * NQC), blk>>>(dl);
    retrv_gemm <<<dim3(4, BATCH * NQC), blk>>>();
    out_gemm   <<<dim3(4, MTOT / 128), blk>>>(Wo, os, out);
}

// round 9
// speedup vs baseline: 2.9827x; 1.5245x over previous
#include <cuda_runtime.h>
#include <cuda_fp16.h>
#include <cstdint>
#include <math.h>

// Problem constants
#define BATCH 4
#define T 4096
#define D 512
#define CHK 128
#define NQC 32
#define WKEYS 384               // decay^256/(1-decay) ~ 8e-5 tail (validated)
#define MTOT 16384
#define XN (BATCH * T * D)
#define WN (D * D)              // 262144 = 2^18

// Scratch (all fp16)
__device__ __align__(16) __half g_xh[XN];
__device__ __align__(16) __half g_wh[4 * WN];
__device__ __align__(16) __half g_q [XN];
__device__ __align__(16) __half g_k [XN];
__device__ __align__(16) __half g_vT[BATCH * D * T];   // V transposed: [b][d][t]
__device__ __align__(16) __half g_ws[BATCH * NQC * CHK * WKEYS];
__device__ __align__(16) __half g_r [XN];

// ---------------------------------------------------------------------------
// helpers
// ---------------------------------------------------------------------------
__device__ __forceinline__ uint32_t f2h2(float x, float y) {
    __half2 h = __floats2half2_rn(x, y);
    return *(uint32_t*)&h;
}
__device__ __forceinline__ uint32_t smem_u32(const void* p) {
    uint32_t a;
    asm("{ .reg .u64 t; cvta.to.shared.u64 t, %1; cvt.u32.u64 %0, t; }"
        : "=r"(a) : "l"(p));
    return a;
}
__device__ __forceinline__ void mma16(float* c, const uint32_t* a,
                                      uint32_t b0, uint32_t b1) {
    asm volatile(
        "mma.sync.aligned.m16n8k16.row.col.f32.f16.f16.f32 "
        "{%0,%1,%2,%3}, {%4,%5,%6,%7}, {%8,%9}, {%0,%1,%2,%3};\n"
        : "+f"(c[0]), "+f"(c[1]), "+f"(c[2]), "+f"(c[3])
        : "r"(a[0]), "r"(a[1]), "r"(a[2]), "r"(a[3]), "r"(b0), "r"(b1));
}
#define LDSM4(d0, d1, d2, d3, a)                                        \
    asm volatile("ldmatrix.sync.aligned.m8n8.x4.shared.b16 "            \
        "{%0,%1,%2,%3}, [%4];"                                          \
        : "=r"(d0), "=r"(d1), "=r"(d2), "=r"(d3) : "r"(a))
#define CP_COMMIT() asm volatile("cp.async.commit_group;" ::: "memory")
#define CP_WAIT(n)  asm volatile("cp.async.wait_group %0;" :: "n"(n) : "memory")

// ---------------------------------------------------------------------------
// Smem tile: 128 rows x 16 halves (K-major), row pitch 12 b32 (24 halves).
// LDSM phase banks: 12r + off mod 32 distinct over 8 consecutive rows ->
// conflict-free. Tile = 1536 b32 (6 KB); stage (A+B) = 12 KB; 3 stages = 36 KB.
// CTA 128x128, 256 threads, 8 warps (2m x 4n), warp tile 64x32.
// ---------------------------------------------------------------------------
#define NST 3
#define TILE_B 6144
#define STG_B  12288

// One 16B cp.async per operand per thread (256 threads cover 128x16 halves).
__device__ __forceinline__ void cp_tile(uint32_t sb, const __half* __restrict__ g,
                                        int ld, int tid)
{
    const int r = tid >> 1, h = tid & 1;
    uint32_t dst = sb + (uint32_t)(r * 48 + 16 * h);
    const __half* src = g + (size_t)r * ld + 8 * h;
    asm volatile("cp.async.ca.shared.global [%0], [%1], 16;"
                 :: "r"(dst), "l"(src) : "memory");
}

// Core: acc += A[128,K] * B[128,K]^T (both K-major half), K = nkt*16.
__device__ __forceinline__ void gemm_core(
    const __half* __restrict__ A, int lda,
    const __half* __restrict__ B, int ldb,
    int nkt, float (*acc)[4],            // [16][4] = acc[mi*4+ni][4]
    uint32_t sb, int tid, int wm, int wn,
    uint32_t offA, uint32_t offB)
{
    cp_tile(sb, A, lda, tid);
    cp_tile(sb + TILE_B, B, ldb, tid);
    CP_COMMIT();
    if (nkt > 1) {
        cp_tile(sb + STG_B, A + 16, lda, tid);
        cp_tile(sb + STG_B + TILE_B, B + 16, ldb, tid);
        CP_COMMIT();
    }
    for (int it = 0; it < nkt; it++) {
        if (it + 1 < nkt) CP_WAIT(1); else CP_WAIT(0);
        __syncthreads();
        if (it + 2 < nkt) {
            uint32_t s2 = sb + (uint32_t)((it + 2) % NST) * STG_B;
            cp_tile(s2, A + (it + 2) * 16, lda, tid);
            cp_tile(s2 + TILE_B, B + (it + 2) * 16, ldb, tid);
            CP_COMMIT();
        }
        uint32_t as = sb + (uint32_t)(it % NST) * STG_B;
        uint32_t bs = as + TILE_B;
        uint32_t a[4][4], b[4][2];
#pragma unroll
        for (int mi = 0; mi < 4; mi++)
            LDSM4(a[mi][0], a[mi][1], a[mi][2], a[mi][3],
                  as + (uint32_t)(wm + mi * 16) * 48 + offA);
#pragma unroll
        for (int j = 0; j < 2; j++) {
            uint32_t d0, d1, d2, d3;
            LDSM4(d0, d1, d2, d3, bs + (uint32_t)(wn + j * 16) * 48 + offB);
            b[2 * j][0] = d0; b[2 * j][1] = d1;
            b[2 * j + 1][0] = d2; b[2 * j + 1][1] = d3;
        }
#pragma unroll
        for (int ni = 0; ni < 4; ni++)
#pragma unroll
            for (int mi = 0; mi < 4; mi++)
                mma16(acc[mi * 4 + ni], a[mi], b[ni][0], b[ni][1]);
    }
}

#define GEMM_PROLOGUE()                                              \
    __shared__ uint32_t smbuf[NST * STG_B / 4];                      \
    float acc[16][4];                                                \
    _Pragma("unroll")                                                \
    for (int i = 0; i < 16; i++)                                     \
        _Pragma("unroll")                                            \
        for (int q = 0; q < 4; q++) acc[i][q] = 0.f;                 \
    const int tid = threadIdx.x;                                     \
    const int warp = tid >> 5, lane = tid & 31;                      \
    const int wm = (warp & 1) * 64, wn = (warp >> 1) * 32;           \
    const int g = lane >> 2, c = lane & 3, sel = lane >> 3;          \
    const uint32_t offA =                                            \
        (uint32_t)(((lane & 7) + 8 * (sel & 1)) * 48 + 16 * (sel >> 1)); \
    const uint32_t offB =                                            \
        (uint32_t)(((lane & 7) + 8 * (sel >> 1)) * 48 + 16 * (sel & 1)); \
    const uint32_t sb = smem_u32(smbuf);

// ---------------------------------------------------------------------------
// Kernel 0: convert x + weights to half.
// ---------------------------------------------------------------------------
__global__ __launch_bounds__(256) void prep(
    const float* __restrict__ x,
    const float* __restrict__ Wq, const float* __restrict__ Wk,
    const float* __restrict__ Wv, const float* __restrict__ Wo)
{
    int i = (blockIdx.x * 256 + threadIdx.x) * 8;
    const float* src;
    __half* dst;
    int off;
    if (i < XN) { src = x; dst = g_xh; off = i; }
    else {
        int j = i - XN;
        int wi = j >> 18;
        off = j & (WN - 1);
        src = (wi == 0) ? Wq : (wi == 1) ? Wk : (wi == 2) ? Wv : Wo;
        dst = g_wh + (wi << 18);
    }
    float4 a = *(const float4*)(src + off);
    float4 b = *(const float4*)(src + off + 4);
    uint4 o;
    o.x = f2h2(a.x, a.y); o.y = f2h2(a.z, a.w);
    o.z = f2h2(b.x, b.y); o.w = f2h2(b.z, b.w);
    *(uint4*)(dst + off) = o;
}

// ---------------------------------------------------------------------------
// Kernel 1: QKV. z=0 -> Q, z=1 -> K (row-major half), z=2 -> V transposed.
// ---------------------------------------------------------------------------
__global__ __launch_bounds__(256, 2) void qkv_gemm()
{
    GEMM_PROLOGUE();
    const int z = blockIdx.z;
    const int row0 = blockIdx.y * 128, col0 = blockIdx.x * 128;
    const __half* A = g_xh + (size_t)row0 * D;
    const __half* B = g_wh + (size_t)z * WN + (size_t)col0 * D;

    gemm_core(A, D, B, D, D / 16, acc, sb, tid, wm, wn, offA, offB);

    if (z < 2) {
        __half* Cp = ((z == 0) ? g_q : g_k) + (size_t)row0 * D + col0;
#pragma unroll
        for (int mi = 0; mi < 4; mi++)
#pragma unroll
            for (int ni = 0; ni < 4; ni++) {
                int row = wm + mi * 16 + g;
                int col = wn + ni * 8 + 2 * c;
                const float* v = acc[mi * 4 + ni];
                *(__half2*)&Cp[(size_t)row * D + col] = __floats2half2_rn(v[0], v[1]);
                *(__half2*)&Cp[(size_t)(row + 8) * D + col] = __floats2half2_rn(v[2], v[3]);
            }
    } else {
        const int b = row0 >> 12;
        const int t0 = row0 & (T - 1);
#pragma unroll
        for (int mi = 0; mi < 4; mi++)
#pragma unroll
            for (int ni = 0; ni < 4; ni++) {
                int t = t0 + wm + mi * 16 + g;
                int col = col0 + wn + ni * 8 + 2 * c;
                const float* v = acc[mi * 4 + ni];
                __half* base0 = g_vT + ((size_t)b * D + col) * T;
                __half* base1 = base0 + T;
                base0[t]     = __float2half_rn(v[0]);
                base1[t]     = __float2half_rn(v[1]);
                base0[t + 8] = __float2half_rn(v[2]);
                base1[t + 8] = __float2half_rn(v[3]);
            }
    }
}

// ---------------------------------------------------------------------------
// Kernel 2: banded scores + decay weights -> g_ws (half).
// ---------------------------------------------------------------------------
__global__ __launch_bounds__(256, 2) void scores_gemm(const float* __restrict__ decay_logit)
{
    const int bid = blockIdx.y;
    const int b = bid >> 5, qc = bid & 31;
    const int col0 = blockIdx.x * 128;
    const int kvalid = T - qc * CHK;
    if (col0 >= kvalid) return;

    GEMM_PROLOGUE();
    const __half* A = g_q + (size_t)(b * T + qc * CHK) * D;
    const __half* B = g_k + (size_t)(b * T + qc * CHK + col0) * D;

    gemm_core(A, D, B, D, D / 16, acc, sb, tid, wm, wn, offA, offB);

    const float dl = *decay_logit;
    const float decay = 1.f / (1.f + expf(-dl));
    const float l2d = log2f(decay);
    __half* WS = g_ws + (size_t)(b * NQC + qc) * CHK * WKEYS;

#pragma unroll
    for (int mi = 0; mi < 4; mi++)
#pragma unroll
        for (int ni = 0; ni < 4; ni++) {
            const float* v = acc[mi * 4 + ni];
#pragma unroll
            for (int hh = 0; hh < 2; hh++) {
                int ti = wm + mi * 16 + g + hh * 8;
                float v0, v1;
#pragma unroll
                for (int e = 0; e < 2; e++) {
                    int jj = col0 + wn + ni * 8 + 2 * c + e;
                    int diff = jj - ti;
                    float w = (diff > 0) ? exp2f((float)(diff - 1) * l2d) : 0.f;
                    float r = v[hh * 2 + e] * w;
                    if (e == 0) v0 = r; else v1 = r;
                }
                int jj0 = col0 + wn + ni * 8 + 2 * c;
                *(__half2*)&WS[(size_t)ti * WKEYS + jj0] = __floats2half2_rn(v0, v1);
            }
        }
}

// ---------------------------------------------------------------------------
// Kernel 3: retrieved = WS @ V_window (NT against g_vT) -> g_r (half).
// ---------------------------------------------------------------------------
__global__ __launch_bounds__(256, 2) void retrv_gemm()
{
    GEMM_PROLOGUE();
    const int bid = blockIdx.y;
    const int b = bid >> 5, qc = bid & 31;
    const int col0 = blockIdx.x * 128;
    const int kvalid = T - qc * CHK;
    const int keff = (kvalid < WKEYS) ? kvalid : WKEYS;
    const int nkt = keff / 16;

    const __half* A = g_ws + (size_t)(b * NQC + qc) * CHK * WKEYS;
    const __half* B = g_vT + ((size_t)b * D + col0) * T + qc * CHK;

    gemm_core(A, WKEYS, B, T, nkt, acc, sb, tid, wm, wn, offA, offB);

    __half* Cp = g_r + (size_t)(b * T + qc * CHK) * D + col0;
#pragma unroll
    for (int mi = 0; mi < 4; mi++)
#pragma unroll
        for (int ni = 0; ni < 4; ni++) {
            int row = wm + mi * 16 + g;
            int col = wn + ni * 8 + 2 * c;
            const float* v = acc[mi * 4 + ni];
            *(__half2*)&Cp[(size_t)row * D + col] = __floats2half2_rn(v[0], v[1]);
            *(__half2*)&Cp[(size_t)(row + 8) * D + col] = __floats2half2_rn(v[2], v[3]);
        }
}

// ---------------------------------------------------------------------------
// Kernel 4: out = (R @ Wo^T) * out_scale   (float output)
// ---------------------------------------------------------------------------
__global__ __launch_bounds__(256, 2) void out_gemm(
    const float* __restrict__ out_scale,
    float* __restrict__ out)
{
    GEMM_PROLOGUE();
    const int row0 = blockIdx.y * 128, col0 = blockIdx.x * 128;
    const __half* A = g_r + (size_t)row0 * D;
    const __half* B = g_wh + 3 * WN + (size_t)col0 * D;

    gemm_core(A, D, B, D, D / 16, acc, sb, tid, wm, wn, offA, offB);

    const float sc = *out_scale;
    float* Cp = out + (size_t)row0 * D + col0;
#pragma unroll
    for (int mi = 0; mi < 4; mi++)
#pragma unroll
        for (int ni = 0; ni < 4; ni++) {
            int row = wm + mi * 16 + g;
            int col = wn + ni * 8 + 2 * c;
            const float* v = acc[mi * 4 + ni];
            *(float2*)&Cp[(size_t)row * D + col] = make_float2(v[0] * sc, v[1] * sc);
            *(float2*)&Cp[(size_t)(row + 8) * D + col] = make_float2(v[2] * sc, v[3] * sc);
        }
}

// ---------------------------------------------------------------------------
extern "C" void kernel_launch(void* const* d_in, const int* in_sizes, int n_in,
                              void* d_out, int out_size)
{
    const float* x  = (const float*)d_in[0];
    const float* Wq = (const float*)d_in[1];
    const float* Wk = (const float*)d_in[2];
    const float* Wv = (const float*)d_in[3];
    const float* Wo = (const float*)d_in[4];
    const float* dl = (const float*)d_in[5];
    const float* os = (const float*)d_in[6];
    float* out = (float*)d_out;

    prep<<<(XN + 4 * WN) / (8 * 256), 256>>>(x, Wq, Wk, Wv, Wo);
    dim3 blk(256);
    qkv_gemm   <<<dim3(4, MTOT / 128, 3), blk>>>();
    scores_gemm<<<dim3(WKEYS / 128, BATCH * NQC), blk>>>(dl);
    retrv_gemm <<<dim3(4, BATCH * NQC), blk>>>();
    out_gemm   <<<dim3(4, MTOT / 128), blk>>>(os, out);
}

// round 10
// speedup vs baseline: 3.0926x; 1.0368x over previous
#include <cuda_runtime.h>
#include <cuda_fp16.h>
#include <cstdint>
#include <math.h>

// Problem constants
#define BATCH 4
#define T 4096
#define D 512
#define CHK 128
#define NQC 32
#define WKEYS 384               // decay^256/(1-decay) ~ 8e-5 tail (validated)
#define MTOT 16384
#define XN (BATCH * T * D)
#define WN (D * D)              // 262144 = 2^18

// Scratch (all fp16)
__device__ __align__(16) __half g_xh[XN];
__device__ __align__(16) __half g_wh[4 * WN];
__device__ __align__(16) __half g_q [XN];
__device__ __align__(16) __half g_k [XN];
__device__ __align__(16) __half g_vT[BATCH * D * T];   // V transposed: [b][d][t]
__device__ __align__(16) __half g_ws[BATCH * NQC * CHK * WKEYS];
__device__ __align__(16) __half g_r [XN];

// ---------------------------------------------------------------------------
// helpers
// ---------------------------------------------------------------------------
__device__ __forceinline__ uint32_t f2h2(float x, float y) {
    __half2 h = __floats2half2_rn(x, y);
    return *(uint32_t*)&h;
}
__device__ __forceinline__ uint32_t smem_u32(const void* p) {
    uint32_t a;
    asm("{ .reg .u64 t; cvta.to.shared.u64 t, %1; cvt.u32.u64 %0, t; }"
        : "=r"(a) : "l"(p));
    return a;
}
__device__ __forceinline__ void mma16(float* c, const uint32_t* a,
                                      uint32_t b0, uint32_t b1) {
    asm volatile(
        "mma.sync.aligned.m16n8k16.row.col.f32.f16.f16.f32 "
        "{%0,%1,%2,%3}, {%4,%5,%6,%7}, {%8,%9}, {%0,%1,%2,%3};\n"
        : "+f"(c[0]), "+f"(c[1]), "+f"(c[2]), "+f"(c[3])
        : "r"(a[0]), "r"(a[1]), "r"(a[2]), "r"(a[3]), "r"(b0), "r"(b1));
}
#define LDSM4(d0, d1, d2, d3, a)                                        \
    asm volatile("ldmatrix.sync.aligned.m8n8.x4.shared.b16 "            \
        "{%0,%1,%2,%3}, [%4];"                                          \
        : "=r"(d0), "=r"(d1), "=r"(d2), "=r"(d3) : "r"(a))
#define CP_COMMIT() asm volatile("cp.async.commit_group;" ::: "memory")
#define CP_WAIT(n)  asm volatile("cp.async.wait_group %0;" :: "n"(n) : "memory")

// ---------------------------------------------------------------------------
// Smem tile: 128 rows x 32 halves (K-major, BK=32), row pitch 80 B (20 b32).
// LDSM phase banks: 20r + off mod 32 distinct over 8 consecutive rows ->
// conflict-free. Tile = 10240 B; stage (A+B) = 20 KB; 3 stages = 60 KB dyn.
// CTA 128x128, 256 threads, 8 warps (2m x 4n), warp tile 64x32. 2 CTAs/SM.
// ---------------------------------------------------------------------------
#define NST 3
#define TILE_B 10240
#define STG_B  20480
#define SMEM_BYTES (NST * STG_B)   // 61440

// Two 16B cp.async per operand per thread (256 threads cover 128x32 halves).
__device__ __forceinline__ void cp_tile(uint32_t sb, const __half* __restrict__ g,
                                        int ld, int tid)
{
    const int r = tid >> 1, h = tid & 1;
    uint32_t dst = sb + (uint32_t)(r * 80 + 16 * h);
    const __half* src = g + (size_t)r * ld + 8 * h;
    asm volatile("cp.async.cg.shared.global [%0], [%1], 16;"
                 :: "r"(dst), "l"(src) : "memory");
    asm volatile("cp.async.cg.shared.global [%0], [%1], 16;"
                 :: "r"(dst + 32), "l"(src + 16) : "memory");
}

// Core: acc += A[128,K] * B[128,K]^T (both K-major half), K = nkt*32.
__device__ __forceinline__ void gemm_core(
    const __half* __restrict__ A, int lda,
    const __half* __restrict__ B, int ldb,
    int nkt, float (*acc)[4],            // acc[mi*4+ni][4]
    uint32_t sb, int tid, int wm, int wn,
    uint32_t offA, uint32_t offB)
{
    cp_tile(sb, A, lda, tid);
    cp_tile(sb + TILE_B, B, ldb, tid);
    CP_COMMIT();
    if (nkt > 1) {
        cp_tile(sb + STG_B, A + 32, lda, tid);
        cp_tile(sb + STG_B + TILE_B, B + 32, ldb, tid);
        CP_COMMIT();
    }
    for (int it = 0; it < nkt; it++) {
        if (it + 1 < nkt) CP_WAIT(1); else CP_WAIT(0);
        __syncthreads();
        if (it + 2 < nkt) {
            uint32_t s2 = sb + (uint32_t)((it + 2) % NST) * STG_B;
            cp_tile(s2, A + (it + 2) * 32, lda, tid);
            cp_tile(s2 + TILE_B, B + (it + 2) * 32, ldb, tid);
            CP_COMMIT();
        }
        uint32_t as = sb + (uint32_t)(it % NST) * STG_B;
        uint32_t bs = as + TILE_B;
#pragma unroll
        for (int ks = 0; ks < 2; ks++) {
            const uint32_t ko = (uint32_t)(ks * 32);   // 16 halves
            uint32_t a[4][4], b[4][2];
#pragma unroll
            for (int mi = 0; mi < 4; mi++)
                LDSM4(a[mi][0], a[mi][1], a[mi][2], a[mi][3],
                      as + (uint32_t)(wm + mi * 16) * 80 + offA + ko);
#pragma unroll
            for (int j = 0; j < 2; j++) {
                uint32_t d0, d1, d2, d3;
                LDSM4(d0, d1, d2, d3,
                      bs + (uint32_t)(wn + j * 16) * 80 + offB + ko);
                b[2 * j][0] = d0; b[2 * j][1] = d1;
                b[2 * j + 1][0] = d2; b[2 * j + 1][1] = d3;
            }
#pragma unroll
            for (int ni = 0; ni < 4; ni++)
#pragma unroll
                for (int mi = 0; mi < 4; mi++)
                    mma16(acc[mi * 4 + ni], a[mi], b[ni][0], b[ni][1]);
        }
    }
}

#define GEMM_PROLOGUE()                                              \
    extern __shared__ uint32_t smbuf[];                              \
    float acc[16][4];                                                \
    _Pragma("unroll")                                                \
    for (int i = 0; i < 16; i++)                                     \
        _Pragma("unroll")                                            \
        for (int q = 0; q < 4; q++) acc[i][q] = 0.f;                 \
    const int tid = threadIdx.x;                                     \
    const int warp = tid >> 5, lane = tid & 31;                      \
    const int wm = (warp & 1) * 64, wn = (warp >> 1) * 32;           \
    const int g = lane >> 2, c = lane & 3, sel = lane >> 3;          \
    const uint32_t offA =                                            \
        (uint32_t)(((lane & 7) + 8 * (sel & 1)) * 80 + 16 * (sel >> 1)); \
    const uint32_t offB =                                            \
        (uint32_t)(((lane & 7) + 8 * (sel >> 1)) * 80 + 16 * (sel & 1)); \
    const uint32_t sb = smem_u32(smbuf);

// ---------------------------------------------------------------------------
// Kernel 0: convert x + weights to half.
// ---------------------------------------------------------------------------
__global__ __launch_bounds__(256) void prep(
    const float* __restrict__ x,
    const float* __restrict__ Wq, const float* __restrict__ Wk,
    const float* __restrict__ Wv, const float* __restrict__ Wo)
{
    int i = (blockIdx.x * 256 + threadIdx.x) * 8;
    const float* src;
    __half* dst;
    int off;
    if (i < XN) { src = x; dst = g_xh; off = i; }
    else {
        int j = i - XN;
        int wi = j >> 18;
        off = j & (WN - 1);
        src = (wi == 0) ? Wq : (wi == 1) ? Wk : (wi == 2) ? Wv : Wo;
        dst = g_wh + (wi << 18);
    }
    float4 a = *(const float4*)(src + off);
    float4 b = *(const float4*)(src + off + 4);
    uint4 o;
    o.x = f2h2(a.x, a.y); o.y = f2h2(a.z, a.w);
    o.z = f2h2(b.x, b.y); o.w = f2h2(b.z, b.w);
    *(uint4*)(dst + off) = o;
}

// ---------------------------------------------------------------------------
// Kernel 1: QKV. z=0 -> Q, z=1 -> K (row-major half), z=2 -> V transposed.
// ---------------------------------------------------------------------------
__global__ __launch_bounds__(256, 2) void qkv_gemm()
{
    GEMM_PROLOGUE();
    const int z = blockIdx.z;
    const int row0 = blockIdx.y * 128, col0 = blockIdx.x * 128;
    const __half* A = g_xh + (size_t)row0 * D;
    const __half* B = g_wh + (size_t)z * WN + (size_t)col0 * D;

    gemm_core(A, D, B, D, D / 32, acc, sb, tid, wm, wn, offA, offB);

    if (z < 2) {
        __half* Cp = ((z == 0) ? g_q : g_k) + (size_t)row0 * D + col0;
#pragma unroll
        for (int mi = 0; mi < 4; mi++)
#pragma unroll
            for (int ni = 0; ni < 4; ni++) {
                int row = wm + mi * 16 + g;
                int col = wn + ni * 8 + 2 * c;
                const float* v = acc[mi * 4 + ni];
                *(__half2*)&Cp[(size_t)row * D + col] = __floats2half2_rn(v[0], v[1]);
                *(__half2*)&Cp[(size_t)(row + 8) * D + col] = __floats2half2_rn(v[2], v[3]);
            }
    } else {
        const int b = row0 >> 12;
        const int t0 = row0 & (T - 1);
#pragma unroll
        for (int mi = 0; mi < 4; mi++)
#pragma unroll
            for (int ni = 0; ni < 4; ni++) {
                int t = t0 + wm + mi * 16 + g;
                int col = col0 + wn + ni * 8 + 2 * c;
                const float* v = acc[mi * 4 + ni];
                __half* base0 = g_vT + ((size_t)b * D + col) * T;
                __half* base1 = base0 + T;
                base0[t]     = __float2half_rn(v[0]);
                base1[t]     = __float2half_rn(v[1]);
                base0[t + 8] = __float2half_rn(v[2]);
                base1[t + 8] = __float2half_rn(v[3]);
            }
    }
}

// ---------------------------------------------------------------------------
// Kernel 2: banded scores + decay weights -> g_ws (half).
// Decay powers via smem table (removes 64 MUFU per thread).
// ---------------------------------------------------------------------------
__global__ __launch_bounds__(256, 2) void scores_gemm(const float* __restrict__ decay_logit)
{
    const int bid = blockIdx.y;
    const int b = bid >> 5, qc = bid & 31;
    const int col0 = blockIdx.x * 128;
    const int kvalid = T - qc * CHK;
    if (col0 >= kvalid) return;

    GEMM_PROLOGUE();
    const __half* A = g_q + (size_t)(b * T + qc * CHK) * D;
    const __half* B = g_k + (size_t)(b * T + qc * CHK + col0) * D;

    gemm_core(A, D, B, D, D / 32, acc, sb, tid, wm, wn, offA, offB);

    // Build decay^i table in (now idle) stage smem.
    __syncthreads();
    float* tbl = (float*)smbuf;
    {
        const float dl = *decay_logit;
        const float l2d = log2f(1.f / (1.f + expf(-dl)));
        for (int i = tid; i < WKEYS; i += 256)
            tbl[i] = exp2f((float)i * l2d);
    }
    __syncthreads();

    __half* WS = g_ws + (size_t)(b * NQC + qc) * CHK * WKEYS;
#pragma unroll
    for (int mi = 0; mi < 4; mi++)
#pragma unroll
        for (int ni = 0; ni < 4; ni++) {
            const float* v = acc[mi * 4 + ni];
#pragma unroll
            for (int hh = 0; hh < 2; hh++) {
                int ti = wm + mi * 16 + g + hh * 8;
                float v0, v1;
#pragma unroll
                for (int e = 0; e < 2; e++) {
                    int jj = col0 + wn + ni * 8 + 2 * c + e;
                    int diff = jj - ti;
                    float w = (diff > 0) ? tbl[diff - 1] : 0.f;
                    float r = v[hh * 2 + e] * w;
                    if (e == 0) v0 = r; else v1 = r;
                }
                int jj0 = col0 + wn + ni * 8 + 2 * c;
                *(__half2*)&WS[(size_t)ti * WKEYS + jj0] = __floats2half2_rn(v0, v1);
            }
        }
}

// ---------------------------------------------------------------------------
// Kernel 3: retrieved = WS @ V_window (NT against g_vT) -> g_r (half).
// ---------------------------------------------------------------------------
__global__ __launch_bounds__(256, 2) void retrv_gemm()
{
    GEMM_PROLOGUE();
    const int bid = blockIdx.y;
    const int b = bid >> 5, qc = bid & 31;
    const int col0 = blockIdx.x * 128;
    const int kvalid = T - qc * CHK;
    const int keff = (kvalid < WKEYS) ? kvalid : WKEYS;
    const int nkt = keff / 32;

    const __half* A = g_ws + (size_t)(b * NQC + qc) * CHK * WKEYS;
    const __half* B = g_vT + ((size_t)b * D + col0) * T + qc * CHK;

    gemm_core(A, WKEYS, B, T, nkt, acc, sb, tid, wm, wn, offA, offB);

    __half* Cp = g_r + (size_t)(b * T + qc * CHK) * D + col0;
#pragma unroll
    for (int mi = 0; mi < 4; mi++)
#pragma unroll
        for (int ni = 0; ni < 4; ni++) {
            int row = wm + mi * 16 + g;
            int col = wn + ni * 8 + 2 * c;
            const float* v = acc[mi * 4 + ni];
            *(__half2*)&Cp[(size_t)row * D + col] = __floats2half2_rn(v[0], v[1]);
            *(__half2*)&Cp[(size_t)(row + 8) * D + col] = __floats2half2_rn(v[2], v[3]);
        }
}

// ---------------------------------------------------------------------------
// Kernel 4: out = (R @ Wo^T) * out_scale   (float output)
// ---------------------------------------------------------------------------
__global__ __launch_bounds__(256, 2) void out_gemm(
    const float* __restrict__ out_scale,
    float* __restrict__ out)
{
    GEMM_PROLOGUE();
    const int row0 = blockIdx.y * 128, col0 = blockIdx.x * 128;
    const __half* A = g_r + (size_t)row0 * D;
    const __half* B = g_wh + 3 * WN + (size_t)col0 * D;

    gemm_core(A, D, B, D, D / 32, acc, sb, tid, wm, wn, offA, offB);

    const float sc = *out_scale;
    float* Cp = out + (size_t)row0 * D + col0;
#pragma unroll
    for (int mi = 0; mi < 4; mi++)
#pragma unroll
        for (int ni = 0; ni < 4; ni++) {
            int row = wm + mi * 16 + g;
            int col = wn + ni * 8 + 2 * c;
            const float* v = acc[mi * 4 + ni];
            *(float2*)&Cp[(size_t)row * D + col] = make_float2(v[0] * sc, v[1] * sc);
            *(float2*)&Cp[(size_t)(row + 8) * D + col] = make_float2(v[2] * sc, v[3] * sc);
        }
}

// ---------------------------------------------------------------------------
extern "C" void kernel_launch(void* const* d_in, const int* in_sizes, int n_in,
                              void* d_out, int out_size)
{
    const float* x  = (const float*)d_in[0];
    const float* Wq = (const float*)d_in[1];
    const float* Wk = (const float*)d_in[2];
    const float* Wv = (const float*)d_in[3];
    const float* Wo = (const float*)d_in[4];
    const float* dl = (const float*)d_in[5];
    const float* os = (const float*)d_in[6];
    float* out = (float*)d_out;

    cudaFuncSetAttribute(qkv_gemm,    cudaFuncAttributeMaxDynamicSharedMemorySize, SMEM_BYTES);
    cudaFuncSetAttribute(scores_gemm, cudaFuncAttributeMaxDynamicSharedMemorySize, SMEM_BYTES);
    cudaFuncSetAttribute(retrv_gemm,  cudaFuncAttributeMaxDynamicSharedMemorySize, SMEM_BYTES);
    cudaFuncSetAttribute(out_gemm,    cudaFuncAttributeMaxDynamicSharedMemorySize, SMEM_BYTES);

    prep<<<(XN + 4 * WN) / (8 * 256), 256>>>(x, Wq, Wk, Wv, Wo);
    dim3 blk(256);
    qkv_gemm   <<<dim3(4, MTOT / 128, 3), blk, SMEM_BYTES>>>();
    scores_gemm<<<dim3(WKEYS / 128, BATCH * NQC), blk, SMEM_BYTES>>>(dl);
    retrv_gemm <<<dim3(4, BATCH * NQC), blk, SMEM_BYTES>>>();
    out_gemm   <<<dim3(4, MTOT / 128), blk, SMEM_BYTES>>>(os, out);
}